// round 2
// baseline (speedup 1.0000x reference)
#include <cuda_runtime.h>
#include <math.h>

#define NMAX 50000
#define EMAX 800000
#define ETOTMAX (EMAX + NMAX)
#define IN_DIM 256
#define OUT_DIM 256   // H*D = 4*64
#define NHEAD 4
#define HDIM 64

// ---------------- scratch (allocation-free: __device__ globals) ----------------
__device__ float    g_h[(size_t)NMAX * OUT_DIM];    // 51.2 MB  transformed features
__device__ float    g_as[NMAX * NHEAD];             // per-node src logits
__device__ float    g_ad[NMAX * NHEAD];             // per-node dst logits
__device__ unsigned g_menc[NMAX * NHEAD];           // segment max (monotonic-encoded)
__device__ float    g_s[NMAX * NHEAD];              // segment sum of exp
__device__ float    g_w[(size_t)ETOTMAX * NHEAD];   // per-edge exp weights (13.6 MB)

// order-preserving float<->uint encoding for atomicMax on floats
__device__ __forceinline__ unsigned encf(float f) {
    unsigned u = __float_as_uint(f);
    return (u & 0x80000000u) ? ~u : (u | 0x80000000u);
}
__device__ __forceinline__ float decf(unsigned u) {
    u = (u & 0x80000000u) ? (u & 0x7fffffffu) : ~u;
    return __uint_as_float(u);
}
#define ENC_NEG_INF 0x007FFFFFu   // encf(-inf)

__device__ __forceinline__ void red_add_v4(float* p, float a, float b, float c, float d) {
    asm volatile("red.global.add.v4.f32 [%0], {%1,%2,%3,%4};"
                 :: "l"(p), "f"(a), "f"(b), "f"(c), "f"(d) : "memory");
}

__device__ __forceinline__ float lrelu(float x) { return x > 0.f ? x : 0.2f * x; }

// ---------------- K0: init out=bias, m=-inf, s=0 ----------------
__global__ void k_init(float* __restrict__ out, const float* __restrict__ bias, int N) {
    int stride = gridDim.x * blockDim.x;
    int gid = blockIdx.x * blockDim.x + threadIdx.x;
    int total = N * OUT_DIM;
    for (int i = gid; i < total; i += stride) out[i] = bias[i & (OUT_DIM - 1)];
    int totalH = N * NHEAD;
    for (int i = gid; i < totalH; i += stride) { g_menc[i] = ENC_NEG_INF; g_s[i] = 0.f; }
}

// ---------------- K1: GEMM h = x @ W   (BM=32, BN=256, BK=32; thread tile 8x4) ----------------
__global__ __launch_bounds__(256) void k_gemm(const float* __restrict__ x,
                                              const float* __restrict__ W, int N) {
    __shared__ float xs[32][32];
    __shared__ float ws[32][256];
    int tid = threadIdx.x;
    int n0 = blockIdx.x * 32;
    int trow = tid >> 6;      // 0..3
    int tcol = tid & 63;      // 0..63

    float acc[8][4];
#pragma unroll
    for (int r = 0; r < 8; r++)
#pragma unroll
        for (int c = 0; c < 4; c++) acc[r][c] = 0.f;

    int lrow = tid >> 3;            // 0..31 (x tile row this thread loads)
    int lkc  = (tid & 7) * 4;       // k-offset within tile (float4)

    for (int k0 = 0; k0 < IN_DIM; k0 += 32) {
        // load x tile [32 rows x 32 k]
        int grow = n0 + lrow;
        float4 xv = make_float4(0.f, 0.f, 0.f, 0.f);
        if (grow < N) xv = *(const float4*)&x[(size_t)grow * IN_DIM + k0 + lkc];
        *(float4*)&xs[lrow][lkc] = xv;
        // load W tile [32 k x 256 cols] (contiguous 8192 floats)
        const float4* Wg = (const float4*)&W[(size_t)k0 * OUT_DIM];
        float4* wsv = (float4*)ws;
#pragma unroll
        for (int i = 0; i < 8; i++) wsv[tid + i * 256] = Wg[tid + i * 256];
        __syncthreads();

#pragma unroll
        for (int k = 0; k < 32; k++) {
            float4 wv = *(float4*)&ws[k][tcol * 4];
            float xr[8];
#pragma unroll
            for (int r = 0; r < 8; r++) xr[r] = xs[trow * 8 + r][k];
#pragma unroll
            for (int r = 0; r < 8; r++) {
                acc[r][0] += xr[r] * wv.x;
                acc[r][1] += xr[r] * wv.y;
                acc[r][2] += xr[r] * wv.z;
                acc[r][3] += xr[r] * wv.w;
            }
        }
        __syncthreads();
    }
#pragma unroll
    for (int r = 0; r < 8; r++) {
        int row = n0 + trow * 8 + r;
        if (row < N) {
            float4 o = make_float4(acc[r][0], acc[r][1], acc[r][2], acc[r][3]);
            *(float4*)&g_h[(size_t)row * OUT_DIM + tcol * 4] = o;
        }
    }
}

// ---------------- K2: per-node attention logits (one warp per node) ----------------
__global__ void k_att(const float* __restrict__ att_src, const float* __restrict__ att_dst, int N) {
    int warp = (blockIdx.x * blockDim.x + threadIdx.x) >> 5;
    int lane = threadIdx.x & 31;
    if (warp >= N) return;
    const float* hp = &g_h[(size_t)warp * OUT_DIM + lane * 8];
    float4 a0 = *(const float4*)hp;
    float4 a1 = *(const float4*)(hp + 4);
    float4 s0 = *(const float4*)&att_src[lane * 8];
    float4 s1 = *(const float4*)&att_src[lane * 8 + 4];
    float4 d0 = *(const float4*)&att_dst[lane * 8];
    float4 d1 = *(const float4*)&att_dst[lane * 8 + 4];
    float ss = a0.x*s0.x + a0.y*s0.y + a0.z*s0.z + a0.w*s0.w
             + a1.x*s1.x + a1.y*s1.y + a1.z*s1.z + a1.w*s1.w;
    float sd = a0.x*d0.x + a0.y*d0.y + a0.z*d0.z + a0.w*d0.w
             + a1.x*d1.x + a1.y*d1.y + a1.z*d1.z + a1.w*d1.w;
    // segmented reduce over groups of 8 lanes (one head per group)
#pragma unroll
    for (int off = 4; off >= 1; off >>= 1) {
        ss += __shfl_down_sync(0xffffffffu, ss, off, 8);
        sd += __shfl_down_sync(0xffffffffu, sd, off, 8);
    }
    if ((lane & 7) == 0) {
        int head = lane >> 3;
        g_as[warp * NHEAD + head] = ss;
        g_ad[warp * NHEAD + head] = sd;
    }
}

// ---------------- K4: segment max over dst ----------------
__global__ void k_max(const int* __restrict__ ei, int E, int N) {
    int Etot = E + N;
    int stride = gridDim.x * blockDim.x;
    for (int i = blockIdx.x * blockDim.x + threadIdx.x; i < Etot; i += stride) {
        int src, dst;
        if (i < E) { src = ei[i]; dst = ei[E + i]; }
        else       { src = dst = i - E; }
        float4 as = *(const float4*)&g_as[src * NHEAD];
        float4 ad = *(const float4*)&g_ad[dst * NHEAD];
        unsigned* mp = &g_menc[dst * NHEAD];
        atomicMax(mp + 0, encf(lrelu(as.x + ad.x)));
        atomicMax(mp + 1, encf(lrelu(as.y + ad.y)));
        atomicMax(mp + 2, encf(lrelu(as.z + ad.z)));
        atomicMax(mp + 3, encf(lrelu(as.w + ad.w)));
    }
}

// ---------------- K5: exp weights + segment sum ----------------
__global__ void k_expsum(const int* __restrict__ ei, int E, int N) {
    int Etot = E + N;
    int stride = gridDim.x * blockDim.x;
    for (int i = blockIdx.x * blockDim.x + threadIdx.x; i < Etot; i += stride) {
        int src, dst;
        if (i < E) { src = ei[i]; dst = ei[E + i]; }
        else       { src = dst = i - E; }
        float4 as = *(const float4*)&g_as[src * NHEAD];
        float4 ad = *(const float4*)&g_ad[dst * NHEAD];
        const unsigned* mp = &g_menc[dst * NHEAD];
        float w0 = expf(lrelu(as.x + ad.x) - decf(mp[0]));
        float w1 = expf(lrelu(as.y + ad.y) - decf(mp[1]));
        float w2 = expf(lrelu(as.z + ad.z) - decf(mp[2]));
        float w3 = expf(lrelu(as.w + ad.w) - decf(mp[3]));
        *(float4*)&g_w[(size_t)i * NHEAD] = make_float4(w0, w1, w2, w3);
        red_add_v4(&g_s[dst * NHEAD], w0, w1, w2, w3);
    }
}

// ---------------- K6: weighted scatter-aggregate (64 threads per edge) ----------------
__global__ __launch_bounds__(256) void k_scatter(const int* __restrict__ ei,
                                                 float* __restrict__ out, int E, int N) {
    int Etot = E + N;
    long long tot = (long long)Etot * 64;
    long long stride = (long long)gridDim.x * blockDim.x;
    for (long long t = (long long)blockIdx.x * blockDim.x + threadIdx.x; t < tot; t += stride) {
        int i = (int)(t >> 6);
        int j = (int)(t & 63);
        int src, dst;
        if (i < E) { src = __ldg(&ei[i]); dst = __ldg(&ei[E + i]); }
        else       { src = dst = i - E; }
        int head = j >> 4;   // 16 float4 chunks per head
        float alpha = g_w[(size_t)i * NHEAD + head] / g_s[dst * NHEAD + head];
        float4 hv = *(const float4*)&g_h[(size_t)src * OUT_DIM + j * 4];
        red_add_v4(&out[(size_t)dst * OUT_DIM + j * 4],
                   alpha * hv.x, alpha * hv.y, alpha * hv.z, alpha * hv.w);
    }
}

// ---------------- launch ----------------
extern "C" void kernel_launch(void* const* d_in, const int* in_sizes, int n_in,
                              void* d_out, int out_size) {
    const float* x       = (const float*)d_in[0];
    const int*   ei      = (const int*)d_in[1];
    const float* W       = (const float*)d_in[2];
    const float* att_src = (const float*)d_in[3];
    const float* att_dst = (const float*)d_in[4];
    const float* bias    = (const float*)d_in[5];
    float* out = (float*)d_out;

    int N = in_sizes[0] / IN_DIM;
    int E = in_sizes[1] / 2;
    int Etot = E + N;

    k_init<<<4096, 256>>>(out, bias, N);
    k_gemm<<<(N + 31) / 32, 256>>>(x, W, N);
    k_att<<<(N * 32 + 255) / 256, 256>>>(att_src, att_dst, N);
    k_max<<<(Etot + 255) / 256, 256>>>(ei, E, N);
    k_expsum<<<(Etot + 255) / 256, 256>>>(ei, E, N);
    long long tot = (long long)Etot * 64;
    int blocks = (int)((tot + 255) / 256);
    k_scatter<<<blocks, 256>>>(ei, out, E, N);
}

// round 3
// speedup vs baseline: 1.8171x; 1.8171x over previous
#include <cuda_runtime.h>
#include <math.h>

#define IN_DIM  256
#define OUT_DIM 256   // H*D = 4*64
#define NHEAD   4
#define NMAX    50000
#define EMAX    800000
#define ETOTMAX (EMAX + NMAX)

// ---------------- scratch (__device__ globals; allocation-free) ----------------
__device__ float g_h[(size_t)NMAX * OUT_DIM];     // 51.2 MB transformed features
__device__ float g_as[NMAX * NHEAD];
__device__ float g_ad[NMAX * NHEAD];
__device__ int   g_cnt[NMAX];
__device__ int   g_fill[NMAX];
__device__ int   g_start[NMAX + 1];
__device__ int   g_csr[ETOTMAX];                  // src node per CSR slot
__device__ float g_w[(size_t)ETOTMAX * NHEAD];    // exp weights per CSR slot
__device__ float g_s[NMAX * NHEAD];               // softmax denominators

typedef unsigned long long u64;

__device__ __forceinline__ u64 pack2(float lo, float hi) {
    u64 r; asm("mov.b64 %0,{%1,%2};" : "=l"(r) : "f"(lo), "f"(hi)); return r;
}
__device__ __forceinline__ u64 ffma2(u64 a, u64 b, u64 c) {
    u64 d; asm("fma.rn.f32x2 %0,%1,%2,%3;" : "=l"(d) : "l"(a), "l"(b), "l"(c)); return d;
}
__device__ __forceinline__ float2 unpack2(u64 v) {
    float2 f; asm("mov.b64 {%0,%1},%2;" : "=f"(f.x), "=f"(f.y) : "l"(v)); return f;
}

__device__ __forceinline__ float lrelu(float x) { return x > 0.f ? x : 0.2f * x; }
__device__ __forceinline__ float4 lrelu4(float4 a) {
    return make_float4(lrelu(a.x), lrelu(a.y), lrelu(a.z), lrelu(a.w));
}
__device__ __forceinline__ float4 add4(float4 a, float4 b) {
    return make_float4(a.x + b.x, a.y + b.y, a.z + b.z, a.w + b.w);
}
__device__ __forceinline__ float4 max4(float4 a, float4 b) {
    return make_float4(fmaxf(a.x, b.x), fmaxf(a.y, b.y), fmaxf(a.z, b.z), fmaxf(a.w, b.w));
}

// ---------------- K0: zero counters ----------------
__global__ void k_zero(int N) {
    int stride = gridDim.x * blockDim.x;
    for (int i = blockIdx.x * blockDim.x + threadIdx.x; i < 2 * N; i += stride) {
        if (i < N) g_cnt[i] = 0; else g_fill[i - N] = 0;
    }
}

// ---------------- K1: GEMM h = x @ W  (BM=64, BN=256, BK=16; 8x8 thread tile, FFMA2) ----------------
#define BM 64
#define BK 16
__global__ __launch_bounds__(256) void k_gemm(const float* __restrict__ x,
                                              const float* __restrict__ W, int N) {
    __shared__ float xsT[BK][BM + 4];   // [k][row], padded
    __shared__ float ws[BK][OUT_DIM];   // [k][col]
    int tid = threadIdx.x;
    int n0 = blockIdx.x * BM;
    int rowt = tid >> 5;     // 0..7  (whole warp same rowt -> xsT reads broadcast)
    int colt = tid & 31;     // 0..31 (cols colt*4..+3 and 128+colt*4..+3 -> conflict-free)

    u64 acc[8][4];
#pragma unroll
    for (int r = 0; r < 8; r++)
#pragma unroll
        for (int c = 0; c < 4; c++) acc[r][c] = 0ull;

    int xrow = tid >> 2;          // 0..63
    int xk = (tid & 3) * 4;       // k offset

    for (int k0 = 0; k0 < IN_DIM; k0 += BK) {
        int grow = n0 + xrow;
        float4 xv = make_float4(0.f, 0.f, 0.f, 0.f);
        if (grow < N) xv = *(const float4*)&x[(size_t)grow * IN_DIM + k0 + xk];
        xsT[xk + 0][xrow] = xv.x;
        xsT[xk + 1][xrow] = xv.y;
        xsT[xk + 2][xrow] = xv.z;
        xsT[xk + 3][xrow] = xv.w;
        const float4* Wg = (const float4*)&W[(size_t)k0 * OUT_DIM];
        float4* wsv = (float4*)ws;
#pragma unroll
        for (int i = 0; i < 4; i++) wsv[tid + i * 256] = Wg[tid + i * 256];
        __syncthreads();

#pragma unroll
        for (int k = 0; k < BK; k++) {
            float4 xa = *(const float4*)&xsT[k][rowt * 8];
            float4 xb = *(const float4*)&xsT[k][rowt * 8 + 4];
            float4 wa = *(const float4*)&ws[k][colt * 4];
            float4 wb = *(const float4*)&ws[k][128 + colt * 4];
            u64 wp0 = pack2(wa.x, wa.y), wp1 = pack2(wa.z, wa.w);
            u64 wp2 = pack2(wb.x, wb.y), wp3 = pack2(wb.z, wb.w);
            float xs8[8] = {xa.x, xa.y, xa.z, xa.w, xb.x, xb.y, xb.z, xb.w};
#pragma unroll
            for (int r = 0; r < 8; r++) {
                u64 xp = pack2(xs8[r], xs8[r]);
                acc[r][0] = ffma2(xp, wp0, acc[r][0]);
                acc[r][1] = ffma2(xp, wp1, acc[r][1]);
                acc[r][2] = ffma2(xp, wp2, acc[r][2]);
                acc[r][3] = ffma2(xp, wp3, acc[r][3]);
            }
        }
        __syncthreads();
    }
#pragma unroll
    for (int r = 0; r < 8; r++) {
        int row = n0 + rowt * 8 + r;
        if (row < N) {
            float2 a0 = unpack2(acc[r][0]), a1 = unpack2(acc[r][1]);
            float2 a2 = unpack2(acc[r][2]), a3 = unpack2(acc[r][3]);
            *(float4*)&g_h[(size_t)row * OUT_DIM + colt * 4] =
                make_float4(a0.x, a0.y, a1.x, a1.y);
            *(float4*)&g_h[(size_t)row * OUT_DIM + 128 + colt * 4] =
                make_float4(a2.x, a2.y, a3.x, a3.y);
        }
    }
}

// ---------------- K2: per-node attention logits (one warp per node) ----------------
__global__ void k_att(const float* __restrict__ att_src, const float* __restrict__ att_dst, int N) {
    int warp = (blockIdx.x * blockDim.x + threadIdx.x) >> 5;
    int lane = threadIdx.x & 31;
    if (warp >= N) return;
    const float* hp = &g_h[(size_t)warp * OUT_DIM + lane * 8];
    float4 a0 = *(const float4*)hp;
    float4 a1 = *(const float4*)(hp + 4);
    float4 s0 = *(const float4*)&att_src[lane * 8];
    float4 s1 = *(const float4*)&att_src[lane * 8 + 4];
    float4 d0 = *(const float4*)&att_dst[lane * 8];
    float4 d1 = *(const float4*)&att_dst[lane * 8 + 4];
    float ss = a0.x*s0.x + a0.y*s0.y + a0.z*s0.z + a0.w*s0.w
             + a1.x*s1.x + a1.y*s1.y + a1.z*s1.z + a1.w*s1.w;
    float sd = a0.x*d0.x + a0.y*d0.y + a0.z*d0.z + a0.w*d0.w
             + a1.x*d1.x + a1.y*d1.y + a1.z*d1.z + a1.w*d1.w;
#pragma unroll
    for (int off = 4; off >= 1; off >>= 1) {
        ss += __shfl_down_sync(0xffffffffu, ss, off, 8);
        sd += __shfl_down_sync(0xffffffffu, sd, off, 8);
    }
    if ((lane & 7) == 0) {
        int head = lane >> 3;
        g_as[warp * NHEAD + head] = ss;
        g_ad[warp * NHEAD + head] = sd;
    }
}

// ---------------- K3a: histogram of dst ----------------
__global__ void k_hist(const int* __restrict__ ei, int E, int N) {
    int Etot = E + N;
    int stride = gridDim.x * blockDim.x;
    for (int i = blockIdx.x * blockDim.x + threadIdx.x; i < Etot; i += stride) {
        int dst = (i < E) ? ei[E + i] : (i - E);
        atomicAdd(&g_cnt[dst], 1);
    }
}

// ---------------- K3b: exclusive scan of g_cnt -> g_start (single block) ----------------
__global__ __launch_bounds__(1024) void k_scan(int N) {
    __shared__ int wsum[32];
    int tid = threadIdx.x;
    int chunk = (N + 1023) >> 10;
    int base = tid * chunk;
    int local = 0;
    for (int i = 0; i < chunk; i++) {
        int idx = base + i;
        if (idx < N) local += g_cnt[idx];
    }
    int lane = tid & 31, w = tid >> 5;
    int v = local;
#pragma unroll
    for (int off = 1; off < 32; off <<= 1) {
        int t = __shfl_up_sync(0xffffffffu, v, off);
        if (lane >= off) v += t;
    }
    if (lane == 31) wsum[w] = v;
    __syncthreads();
    if (w == 0) {
        int sv = wsum[lane];
#pragma unroll
        for (int off = 1; off < 32; off <<= 1) {
            int t = __shfl_up_sync(0xffffffffu, sv, off);
            if (lane >= off) sv += t;
        }
        wsum[lane] = sv;
    }
    __syncthreads();
    int excl = v - local + (w > 0 ? wsum[w - 1] : 0);
    int run = excl;
    for (int i = 0; i < chunk; i++) {
        int idx = base + i;
        if (idx < N) {
            g_start[idx] = run;
            run += g_cnt[idx];
        }
    }
    if (tid == 1023) g_start[N] = run;
}

// ---------------- K3c: fill CSR ----------------
__global__ void k_fill(const int* __restrict__ ei, int E, int N) {
    int Etot = E + N;
    int stride = gridDim.x * blockDim.x;
    for (int i = blockIdx.x * blockDim.x + threadIdx.x; i < Etot; i += stride) {
        int src, dst;
        if (i < E) { src = ei[i]; dst = ei[E + i]; }
        else       { src = dst = i - E; }
        int pos = g_start[dst] + atomicAdd(&g_fill[dst], 1);
        g_csr[pos] = src;
    }
}

// ---------------- K4: per-node softmax over CSR segment (8 lanes per node) ----------------
__global__ void k_soft(int N) {
    int g = blockIdx.x * blockDim.x + threadIdx.x;
    int node = g >> 3;
    int sub = g & 7;
    bool valid = node < N;
    int nc = valid ? node : (N - 1);
    int start = g_start[nc], end = g_start[nc + 1];
    float4 ad = *(const float4*)&g_ad[nc * NHEAD];
    float4 m = make_float4(-3.4e38f, -3.4e38f, -3.4e38f, -3.4e38f);
    for (int p = start + sub; p < end; p += 8) {
        int src = g_csr[p];
        float4 as = *(const float4*)&g_as[src * NHEAD];
        m = max4(m, lrelu4(add4(as, ad)));
    }
#pragma unroll
    for (int off = 4; off >= 1; off >>= 1) {
        m.x = fmaxf(m.x, __shfl_xor_sync(0xffffffffu, m.x, off, 8));
        m.y = fmaxf(m.y, __shfl_xor_sync(0xffffffffu, m.y, off, 8));
        m.z = fmaxf(m.z, __shfl_xor_sync(0xffffffffu, m.z, off, 8));
        m.w = fmaxf(m.w, __shfl_xor_sync(0xffffffffu, m.w, off, 8));
    }
    float4 s = make_float4(0.f, 0.f, 0.f, 0.f);
    for (int p = start + sub; p < end; p += 8) {
        int src = g_csr[p];
        float4 as = *(const float4*)&g_as[src * NHEAD];
        float4 e = lrelu4(add4(as, ad));
        float4 wv = make_float4(__expf(e.x - m.x), __expf(e.y - m.y),
                                __expf(e.z - m.z), __expf(e.w - m.w));
        if (valid) *(float4*)&g_w[(size_t)p * NHEAD] = wv;
        s = add4(s, wv);
    }
#pragma unroll
    for (int off = 4; off >= 1; off >>= 1) {
        s.x += __shfl_xor_sync(0xffffffffu, s.x, off, 8);
        s.y += __shfl_xor_sync(0xffffffffu, s.y, off, 8);
        s.z += __shfl_xor_sync(0xffffffffu, s.z, off, 8);
        s.w += __shfl_xor_sync(0xffffffffu, s.w, off, 8);
    }
    if (valid && sub == 0) *(float4*)&g_s[nc * NHEAD] = s;
}

// ---------------- K5: aggregate (64 threads per node, register accum, single store) ----------------
__global__ __launch_bounds__(256) void k_agg(const float* __restrict__ bias,
                                             float* __restrict__ out, int N) {
    int node = blockIdx.x * 4 + (threadIdx.x >> 6);
    if (node >= N) return;
    int j = threadIdx.x & 63;
    int head = j >> 4;
    int start = g_start[node], end = g_start[node + 1];
    float inv_s = __frcp_rn(g_s[node * NHEAD + head]);
    float4 acc = make_float4(0.f, 0.f, 0.f, 0.f);
    for (int p = start; p < end; p++) {
        int src = __ldg(&g_csr[p]);
        float alpha = g_w[(size_t)p * NHEAD + head] * inv_s;
        float4 hv = *(const float4*)&g_h[(size_t)src * OUT_DIM + j * 4];
        acc.x += alpha * hv.x;
        acc.y += alpha * hv.y;
        acc.z += alpha * hv.z;
        acc.w += alpha * hv.w;
    }
    float4 bv = *(const float4*)&bias[j * 4];
    acc = add4(acc, bv);
    *(float4*)&out[(size_t)node * OUT_DIM + j * 4] = acc;
}

// ---------------- launch ----------------
extern "C" void kernel_launch(void* const* d_in, const int* in_sizes, int n_in,
                              void* d_out, int out_size) {
    const float* x       = (const float*)d_in[0];
    const int*   ei      = (const int*)d_in[1];
    const float* W       = (const float*)d_in[2];
    const float* att_src = (const float*)d_in[3];
    const float* att_dst = (const float*)d_in[4];
    const float* bias    = (const float*)d_in[5];
    float* out = (float*)d_out;

    int N = in_sizes[0] / IN_DIM;
    int E = in_sizes[1] / 2;
    int Etot = E + N;

    k_zero<<<(2 * N + 255) / 256, 256>>>(N);
    k_gemm<<<(N + BM - 1) / BM, 256>>>(x, W, N);
    k_att<<<(N * 32 + 255) / 256, 256>>>(att_src, att_dst, N);
    k_hist<<<(Etot + 255) / 256, 256>>>(ei, E, N);
    k_scan<<<1, 1024>>>(N);
    k_fill<<<(Etot + 255) / 256, 256>>>(ei, E, N);
    k_soft<<<(N * 8 + 255) / 256, 256>>>(N);
    k_agg<<<(N + 3) / 4, 256>>>(bias, out, N);
}